// round 2
// baseline (speedup 1.0000x reference)
#include <cuda_runtime.h>

#define DIM 31
#define PAD 32
#define NMAX 500000
#define EMAX 2000000
#define GMAX 4096
#define BN_EPS 1e-5f

// ---------------- scratch ----------------
__device__ float g_y[(size_t)NMAX * PAD];     // node features (raw relu outputs / input x)
__device__ float g_agg[(size_t)NMAX * PAD];   // gathered neighbor sums
__device__ int   g_cnt[NMAX];
__device__ int   g_rowptr[NMAX + 1];
__device__ int   g_cursor[NMAX];
__device__ int   g_perm[EMAX];
__device__ float g_deg[NMAX];
__device__ int   g_bsums[1024];
__device__ float g_sums[5 * 64];              // per-layer colsum (c) + sumsq (32+c)
__device__ float g_pooled[GMAX * PAD];
__device__ float g_gcnt[GMAX];
__device__ float g_ha[GMAX * 256];
__device__ float g_hb[GMAX * 256];
__device__ float g_c1[GMAX * 1024];
__device__ float g_c2[GMAX * 256];

// ---------------- init: pack x, zero cnt/sums/pooled/gcnt ----------------
__global__ void k_init(const float* __restrict__ x, int N) {
    int stride = gridDim.x * blockDim.x;
    int tid0 = blockIdx.x * blockDim.x + threadIdx.x;
    int total = N * PAD;
    for (int t = tid0; t < total; t += stride) {
        int c = t & (PAD - 1);
        int i = t >> 5;
        g_y[t] = (c < DIM) ? x[i * DIM + c] : 0.f;
    }
    for (int t = tid0; t < N; t += stride) g_cnt[t] = 0;
    for (int t = tid0; t < GMAX * PAD; t += stride) g_pooled[t] = 0.f;
    for (int t = tid0; t < GMAX; t += stride) g_gcnt[t] = 0.f;
    if (blockIdx.x == 0) {
        for (int t = threadIdx.x; t < 5 * 64; t += blockDim.x) g_sums[t] = 0.f;
    }
}

// ---------------- CSR build ----------------
__global__ void k_count(const int* __restrict__ dst, int E) {
    for (int e = blockIdx.x * blockDim.x + threadIdx.x; e < E;
         e += gridDim.x * blockDim.x)
        atomicAdd(&g_cnt[__ldg(dst + e)], 1);
}

__global__ void k_scan1(int N) {
    __shared__ int s[512];
    int i = blockIdx.x * 512 + threadIdx.x;
    s[threadIdx.x] = (i < N) ? g_cnt[i] : 0;
    __syncthreads();
    for (int o = 256; o > 0; o >>= 1) {
        if (threadIdx.x < o) s[threadIdx.x] += s[threadIdx.x + o];
        __syncthreads();
    }
    if (threadIdx.x == 0) g_bsums[blockIdx.x] = s[0];
}

__global__ void k_scan2(int NB) {
    __shared__ int s[1024];
    int i = threadIdx.x;
    int v = (i < NB) ? g_bsums[i] : 0;
    s[i] = v;
    __syncthreads();
    for (int o = 1; o < 1024; o <<= 1) {
        int t = (i >= o) ? s[i - o] : 0;
        __syncthreads();
        s[i] += t;
        __syncthreads();
    }
    if (i < NB) g_bsums[i] = s[i] - v;  // exclusive
}

__global__ void k_scan3(int N) {
    __shared__ int s[512];
    int i = blockIdx.x * 512 + threadIdx.x;
    int c = (i < N) ? g_cnt[i] : 0;
    s[threadIdx.x] = c;
    __syncthreads();
    for (int o = 1; o < 512; o <<= 1) {
        int t = (threadIdx.x >= o) ? s[threadIdx.x - o] : 0;
        __syncthreads();
        s[threadIdx.x] += t;
        __syncthreads();
    }
    int ex = s[threadIdx.x] - c + g_bsums[blockIdx.x];
    if (i < N) {
        g_rowptr[i] = ex;
        g_cursor[i] = ex;
        g_deg[i] = (float)c;
        if (i == N - 1) g_rowptr[N] = ex + c;
    }
}

__global__ void k_fill(const int* __restrict__ src, const int* __restrict__ dst, int E) {
    for (int e = blockIdx.x * blockDim.x + threadIdx.x; e < E;
         e += gridDim.x * blockDim.x) {
        int d = __ldg(dst + e);
        int p = atomicAdd(&g_cursor[d], 1);
        g_perm[p] = __ldg(src + e);
    }
}

// ---------------- gather: agg[n] = sum over in-neighbors of y[src] (raw) ----------------
__global__ void k_gather(int N) {
    int t = blockIdx.x * blockDim.x + threadIdx.x;
    int n = t >> 3, g = t & 7;
    if (n >= N) return;
    int beg = __ldg(g_rowptr + n), end = __ldg(g_rowptr + n + 1);
    float4 acc = make_float4(0.f, 0.f, 0.f, 0.f);
    int p = beg;
    for (; p + 1 < end; p += 2) {
        int s0 = __ldg(g_perm + p);
        int s1 = __ldg(g_perm + p + 1);
        float4 v0 = *(const float4*)(g_y + (size_t)s0 * PAD + g * 4);
        float4 v1 = *(const float4*)(g_y + (size_t)s1 * PAD + g * 4);
        acc.x += v0.x + v1.x;
        acc.y += v0.y + v1.y;
        acc.z += v0.z + v1.z;
        acc.w += v0.w + v1.w;
    }
    if (p < end) {
        int s0 = __ldg(g_perm + p);
        float4 v0 = *(const float4*)(g_y + (size_t)s0 * PAD + g * 4);
        acc.x += v0.x;
        acc.y += v0.y;
        acc.z += v0.z;
        acc.w += v0.w;
    }
    ((float4*)g_agg)[(size_t)n * 8 + g] = acc;
}

// ---------------- MLP with fused BN-affine input + fused column stats ----------------
__global__ void __launch_bounds__(128) k_mlp(const float* __restrict__ W1,
                                             const float* __restrict__ b1,
                                             const float* __restrict__ W2,
                                             const float* __restrict__ b2,
                                             const float* __restrict__ gammaP,
                                             const float* __restrict__ betaP,
                                             const float* __restrict__ sumsP,
                                             float* __restrict__ sumsC,
                                             int N, float invN) {
    __shared__ float sW1[DIM * PAD], sW2[DIM * PAD];
    __shared__ float sb1[PAD], sb2[PAD], ssc[PAD], ssf[PAD];
    for (int idx = threadIdx.x; idx < DIM * DIM; idx += 128) {
        int i = idx / DIM, o = idx % DIM;
        sW1[i * PAD + o] = W1[idx];
        sW2[i * PAD + o] = W2[idx];
    }
    if (threadIdx.x < PAD) {
        int c = threadIdx.x;
        sb1[c] = (c < DIM) ? b1[c] : 0.f;
        sb2[c] = (c < DIM) ? b2[c] : 0.f;
        float sc = 0.f, sf = 0.f;
        if (c < DIM) {
            sc = 1.f;
            if (sumsP) {
                float m = sumsP[c] * invN;
                float var = sumsP[PAD + c] * invN - m * m;
                float istd = rsqrtf(var + BN_EPS);
                sc = gammaP[c] * istd;
                sf = betaP[c] - m * sc;
            }
        }
        ssc[c] = sc;
        ssf[c] = sf;
    }
    __syncthreads();

    int n = blockIdx.x * 128 + threadIdx.x;
    bool act = n < N;

    float h[PAD];
    if (act) {
        const float4* yr = (const float4*)(g_y + (size_t)n * PAD);
        const float4* ar = (const float4*)(g_agg + (size_t)n * PAD);
        float dp1 = g_deg[n] + 1.f;
#pragma unroll
        for (int g = 0; g < 8; g++) {
            float4 a = yr[g];
            float4 s = ar[g];
            int c = 4 * g;
            h[c + 0] = ssc[c + 0] * (a.x + s.x) + dp1 * ssf[c + 0];
            h[c + 1] = ssc[c + 1] * (a.y + s.y) + dp1 * ssf[c + 1];
            h[c + 2] = ssc[c + 2] * (a.z + s.z) + dp1 * ssf[c + 2];
            h[c + 3] = ssc[c + 3] * (a.w + s.w) + dp1 * ssf[c + 3];
        }
    } else {
#pragma unroll
        for (int c = 0; c < PAD; c++) h[c] = 0.f;
    }

    float acc[DIM];
#pragma unroll
    for (int o = 0; o < DIM; o++) acc[o] = sb1[o];
#pragma unroll
    for (int i = 0; i < DIM; i++) {
        float xi = h[i];
        const float4* wr = (const float4*)(sW1 + i * PAD);
#pragma unroll
        for (int gq = 0; gq < 8; gq++) {
            float4 w = wr[gq];
            int o = gq * 4;
            acc[o + 0] += xi * w.x;
            acc[o + 1] += xi * w.y;
            acc[o + 2] += xi * w.z;
            if (o + 3 < DIM) acc[o + 3] += xi * w.w;
        }
    }
    float tt[DIM];
#pragma unroll
    for (int o = 0; o < DIM; o++) tt[o] = fmaxf(acc[o], 0.f);

#pragma unroll
    for (int o = 0; o < DIM; o++) acc[o] = sb2[o];
#pragma unroll
    for (int i = 0; i < DIM; i++) {
        float xi = tt[i];
        const float4* wr = (const float4*)(sW2 + i * PAD);
#pragma unroll
        for (int gq = 0; gq < 8; gq++) {
            float4 w = wr[gq];
            int o = gq * 4;
            acc[o + 0] += xi * w.x;
            acc[o + 1] += xi * w.y;
            acc[o + 2] += xi * w.z;
            if (o + 3 < DIM) acc[o + 3] += xi * w.w;
        }
    }

    float yv[PAD];
#pragma unroll
    for (int o = 0; o < DIM; o++) yv[o] = act ? fmaxf(acc[o], 0.f) : 0.f;
    yv[31] = 0.f;

    if (act) {
        float4* outp = (float4*)(g_y + (size_t)n * PAD);
#pragma unroll
        for (int g = 0; g < 8; g++)
            outp[g] = make_float4(yv[4 * g], yv[4 * g + 1], yv[4 * g + 2], yv[4 * g + 3]);
    }

    // fused column stats: warp-shuffle reduce, lane 0 REDs to global
#pragma unroll
    for (int c = 0; c < DIM; c++) {
        float s = yv[c];
        float q = s * s;
#pragma unroll
        for (int o = 16; o > 0; o >>= 1) {
            s += __shfl_xor_sync(0xffffffffu, s, o);
            q += __shfl_xor_sync(0xffffffffu, q, o);
        }
        if ((threadIdx.x & 31) == 0) {
            atomicAdd(&sumsC[c], s);
            atomicAdd(&sumsC[PAD + c], q);
        }
    }
}

// ---------------- pooling: raw sums + counts, warp-aggregated ----------------
__global__ void k_pool(const int* __restrict__ batch, int N) {
    int t = blockIdx.x * blockDim.x + threadIdx.x;
    int n = t >> 3, g = t & 7, lane = threadIdx.x & 31;
    int b = -1;
    float4 v = make_float4(0.f, 0.f, 0.f, 0.f);
    if (n < N) {
        b = __ldg(batch + n);
        v = ((const float4*)g_y)[(size_t)n * 8 + g];
    }
    int b1 = __shfl_xor_sync(0xffffffffu, b, 8);
    int b2 = __shfl_xor_sync(0xffffffffu, b, 16);
    int b3 = __shfl_xor_sync(0xffffffffu, b, 24);
    bool allsame = (b == b1) && (b == b2) && (b == b3);  // uniform across warp
    if (allsame) {
        v.x += __shfl_xor_sync(0xffffffffu, v.x, 8);
        v.y += __shfl_xor_sync(0xffffffffu, v.y, 8);
        v.z += __shfl_xor_sync(0xffffffffu, v.z, 8);
        v.w += __shfl_xor_sync(0xffffffffu, v.w, 8);
        v.x += __shfl_xor_sync(0xffffffffu, v.x, 16);
        v.y += __shfl_xor_sync(0xffffffffu, v.y, 16);
        v.z += __shfl_xor_sync(0xffffffffu, v.z, 16);
        v.w += __shfl_xor_sync(0xffffffffu, v.w, 16);
        if (b >= 0 && lane < 8) {
            float* p = g_pooled + (size_t)b * PAD + g * 4;
            atomicAdd(p + 0, v.x);
            atomicAdd(p + 1, v.y);
            atomicAdd(p + 2, v.z);
            if (g < 7) atomicAdd(p + 3, v.w);
            if (lane == 0) atomicAdd(&g_gcnt[b], 4.f);
        }
    } else {
        if (b >= 0) {
            float* p = g_pooled + (size_t)b * PAD + g * 4;
            atomicAdd(p + 0, v.x);
            atomicAdd(p + 1, v.y);
            atomicAdd(p + 2, v.z);
            if (g < 7) atomicAdd(p + 3, v.w);
            if (g == 0) atomicAdd(&g_gcnt[b], 1.f);
        }
    }
}

// ---------------- per-graph fc with layer-4 BN affine applied to pooled ----------------
__global__ void k_fcbr(const float* __restrict__ W, const float* __restrict__ bb,
                       const float* __restrict__ gamma4, const float* __restrict__ beta4,
                       float* __restrict__ out, int G, float invN) {
    __shared__ float p[PAD];
    int g = blockIdx.x;
    if (threadIdx.x < PAD) {
        int c = threadIdx.x;
        float val = 0.f;
        if (c < DIM) {
            const float* s = g_sums + 4 * 64;
            float m = s[c] * invN;
            float var = s[PAD + c] * invN - m * m;
            float istd = rsqrtf(var + BN_EPS);
            float sc = gamma4[c] * istd;
            float sf = beta4[c] - m * sc;
            val = g_pooled[g * PAD + c] * sc + g_gcnt[g] * sf;
        }
        p[c] = val;
    }
    __syncthreads();
    int o = threadIdx.x;
    float acc = __ldg(bb + o);
#pragma unroll
    for (int i = 0; i < DIM; i++) acc += p[i] * __ldg(W + i * 256 + o);
    out[g * 256 + o] = fmaxf(acc, 0.f);
}

// ---------------- tiled SGEMM: C = act((A [+A2]) @ B + bias) ----------------
template <bool SUM2, bool RELU>
__global__ void k_gemm(const float* __restrict__ A, const float* __restrict__ A2,
                       const float* __restrict__ B, const float* __restrict__ bias,
                       float* __restrict__ C, int M, int N, int K) {
    const int BM = 64, BN = 64, BK = 16;
    __shared__ float As[BK][BM];
    __shared__ float Bs[BK][BN];
    int tx = threadIdx.x % 16, ty = threadIdx.x / 16;
    int row0 = blockIdx.y * BM, col0 = blockIdx.x * BN;
    float acc[4][4] = {};
    for (int k0 = 0; k0 < K; k0 += BK) {
        for (int i = threadIdx.x; i < BM * BK; i += 256) {
            int r = i / BK, c = i % BK;
            float v = A[(size_t)(row0 + r) * K + k0 + c];
            if (SUM2) v += A2[(size_t)(row0 + r) * K + k0 + c];
            As[c][r] = v;
        }
        for (int i = threadIdx.x; i < BK * BN; i += 256) {
            int r = i / BN, c = i % BN;
            Bs[r][c] = B[(size_t)(k0 + r) * N + col0 + c];
        }
        __syncthreads();
#pragma unroll
        for (int k = 0; k < BK; k++) {
            float a[4], bv[4];
#pragma unroll
            for (int u = 0; u < 4; u++) a[u] = As[k][ty * 4 + u];
#pragma unroll
            for (int u = 0; u < 4; u++) bv[u] = Bs[k][tx * 4 + u];
#pragma unroll
            for (int u = 0; u < 4; u++)
#pragma unroll
                for (int w = 0; w < 4; w++) acc[u][w] += a[u] * bv[w];
        }
        __syncthreads();
    }
#pragma unroll
    for (int u = 0; u < 4; u++)
#pragma unroll
        for (int w = 0; w < 4; w++) {
            int r = row0 + ty * 4 + u;
            int cc = col0 + tx * 4 + w;
            float val = acc[u][w] + bias[cc];
            if (RELU) val = fmaxf(val, 0.f);
            C[(size_t)r * N + cc] = val;
        }
}

// ---------------- final projection ----------------
__global__ void k_out(const float* __restrict__ W, const float* __restrict__ b,
                      float* __restrict__ out, int G) {
    __shared__ float sW[512];
    for (int i = threadIdx.x; i < 512; i += blockDim.x) sW[i] = W[i];
    __syncthreads();
    int g = blockIdx.x * blockDim.x + threadIdx.x;
    if (g >= G) return;
    const float4* row = (const float4*)(g_c2 + (size_t)g * 256);
    float a0 = b[0], a1 = b[1];
#pragma unroll 8
    for (int i = 0; i < 64; i++) {
        float4 v = row[i];
        int o = i * 4;
        a0 += v.x * sW[2 * o + 0] + v.y * sW[2 * o + 2] + v.z * sW[2 * o + 4] + v.w * sW[2 * o + 6];
        a1 += v.x * sW[2 * o + 1] + v.y * sW[2 * o + 3] + v.z * sW[2 * o + 5] + v.w * sW[2 * o + 7];
    }
    out[g * 2 + 0] = a0;
    out[g * 2 + 1] = a1;
}

// ---------------- launch ----------------
extern "C" void kernel_launch(void* const* d_in, const int* in_sizes, int n_in,
                              void* d_out, int out_size) {
    const float* x_a = (const float*)d_in[0];
    const int* ei_a = (const int*)d_in[1];
    const int* batch_a = (const int*)d_in[2];
    const float* x_b = (const float*)d_in[3];
    const int* ei_b = (const int*)d_in[4];
    const int* batch_b = (const int*)d_in[5];
    const float* W1s = (const float*)d_in[6];
    const float* b1s = (const float*)d_in[7];
    const float* W2s = (const float*)d_in[8];
    const float* b2s = (const float*)d_in[9];
    const float* gammas = (const float*)d_in[10];
    const float* betas = (const float*)d_in[11];
    const float* fcxW = (const float*)d_in[12];
    const float* fcxb = (const float*)d_in[13];
    const float* fc1W = (const float*)d_in[14];
    const float* fc1b = (const float*)d_in[15];
    const float* fc2W = (const float*)d_in[16];
    const float* fc2b = (const float*)d_in[17];
    const float* outW = (const float*)d_in[18];
    const float* outb = (const float*)d_in[19];

    int N = in_sizes[0] / DIM;
    int E = in_sizes[1] / 2;
    int G = out_size / 2;
    float invN = 1.f / (float)N;
    int NB = (N + 511) / 512;

    float* sums_ptr;
    float* ha_ptr;
    float* hb_ptr;
    float* c1_ptr;
    float* c2_ptr;
    cudaGetSymbolAddress((void**)&sums_ptr, g_sums);
    cudaGetSymbolAddress((void**)&ha_ptr, g_ha);
    cudaGetSymbolAddress((void**)&hb_ptr, g_hb);
    cudaGetSymbolAddress((void**)&c1_ptr, g_c1);
    cudaGetSymbolAddress((void**)&c2_ptr, g_c2);

    for (int br = 0; br < 2; br++) {
        const float* x = br ? x_b : x_a;
        const int* ei = br ? ei_b : ei_a;
        const int* batch = br ? batch_b : batch_a;
        float* h = br ? hb_ptr : ha_ptr;

        k_init<<<2048, 256>>>(x, N);
        k_count<<<2048, 256>>>(ei + E, E);
        k_scan1<<<NB, 512>>>(N);
        k_scan2<<<1, 1024>>>(NB);
        k_scan3<<<NB, 512>>>(N);
        k_fill<<<2048, 256>>>(ei, ei + E, E);

        for (int l = 0; l < 5; l++) {
            k_gather<<<(N * 8 + 255) / 256, 256>>>(N);
            const float* sumsP = (l == 0) ? nullptr : sums_ptr + (l - 1) * 64;
            const float* gP = (l == 0) ? nullptr : gammas + (l - 1) * DIM;
            const float* bP = (l == 0) ? nullptr : betas + (l - 1) * DIM;
            k_mlp<<<(N + 127) / 128, 128>>>(W1s + l * DIM * DIM, b1s + l * DIM,
                                            W2s + l * DIM * DIM, b2s + l * DIM,
                                            gP, bP, sumsP, sums_ptr + l * 64, N, invN);
        }
        k_pool<<<(N * 8 + 255) / 256, 256>>>(batch, N);
        k_fcbr<<<G, 256>>>(fcxW, fcxb, gammas + 4 * DIM, betas + 4 * DIM, h, G, invN);
    }

    dim3 g1(1024 / 64, G / 64);
    k_gemm<true, true><<<g1, 256>>>(ha_ptr, hb_ptr, fc1W, fc1b, c1_ptr, G, 1024, 256);
    dim3 g2(256 / 64, G / 64);
    k_gemm<false, true><<<g2, 256>>>(c1_ptr, nullptr, fc2W, fc2b, c2_ptr, G, 256, 1024);
    k_out<<<(G + 255) / 256, 256>>>(outW, outb, (float*)d_out, G);
}

// round 3
// speedup vs baseline: 3.2188x; 3.2188x over previous
#include <cuda_runtime.h>

#define DIM 31
#define PAD 32
#define NMAX 500000
#define EMAX 2000000
#define GMAX 4096
#define BN_EPS 1e-5f
#define NPB_MAX 4096

// ---------------- scratch ----------------
__device__ float g_y[(size_t)NMAX * PAD];     // node features (raw relu outputs / input x)
__device__ float g_agg[(size_t)NMAX * PAD];   // self + gathered neighbor sums
__device__ int   g_cnt[NMAX];
__device__ int   g_rowptr[NMAX + 1];
__device__ int   g_cursor[NMAX];
__device__ int   g_perm[EMAX];
__device__ float g_deg[NMAX];
__device__ int   g_bsums[1024];
__device__ float g_partial[(size_t)NPB_MAX * 64];  // per-block column stats
__device__ float g_sums[5 * 64];              // per-layer colsum (c) + sumsq (32+c)
__device__ float g_pooled[GMAX * PAD];
__device__ float g_gcnt[GMAX];
__device__ float g_ha[GMAX * 256];
__device__ float g_hb[GMAX * 256];
__device__ float g_c1[GMAX * 1024];
__device__ float g_c2[GMAX * 256];

// ---------------- init: pack x, zero cnt/pooled/gcnt ----------------
__global__ void k_init(const float* __restrict__ x, int N) {
    int stride = gridDim.x * blockDim.x;
    int tid0 = blockIdx.x * blockDim.x + threadIdx.x;
    int total = N * PAD;
    for (int t = tid0; t < total; t += stride) {
        int c = t & (PAD - 1);
        int i = t >> 5;
        g_y[t] = (c < DIM) ? x[i * DIM + c] : 0.f;
    }
    for (int t = tid0; t < N; t += stride) g_cnt[t] = 0;
    for (int t = tid0; t < GMAX * PAD; t += stride) g_pooled[t] = 0.f;
    for (int t = tid0; t < GMAX; t += stride) g_gcnt[t] = 0.f;
}

// ---------------- CSR build ----------------
__global__ void k_count(const int* __restrict__ dst, int E) {
    for (int e = blockIdx.x * blockDim.x + threadIdx.x; e < E;
         e += gridDim.x * blockDim.x)
        atomicAdd(&g_cnt[__ldg(dst + e)], 1);
}

__global__ void k_scan1(int N) {
    __shared__ int s[512];
    int i = blockIdx.x * 512 + threadIdx.x;
    s[threadIdx.x] = (i < N) ? g_cnt[i] : 0;
    __syncthreads();
    for (int o = 256; o > 0; o >>= 1) {
        if (threadIdx.x < o) s[threadIdx.x] += s[threadIdx.x + o];
        __syncthreads();
    }
    if (threadIdx.x == 0) g_bsums[blockIdx.x] = s[0];
}

__global__ void k_scan2(int NB) {
    __shared__ int s[1024];
    int i = threadIdx.x;
    int v = (i < NB) ? g_bsums[i] : 0;
    s[i] = v;
    __syncthreads();
    for (int o = 1; o < 1024; o <<= 1) {
        int t = (i >= o) ? s[i - o] : 0;
        __syncthreads();
        s[i] += t;
        __syncthreads();
    }
    if (i < NB) g_bsums[i] = s[i] - v;  // exclusive
}

__global__ void k_scan3(int N) {
    __shared__ int s[512];
    int i = blockIdx.x * 512 + threadIdx.x;
    int c = (i < N) ? g_cnt[i] : 0;
    s[threadIdx.x] = c;
    __syncthreads();
    for (int o = 1; o < 512; o <<= 1) {
        int t = (threadIdx.x >= o) ? s[threadIdx.x - o] : 0;
        __syncthreads();
        s[threadIdx.x] += t;
        __syncthreads();
    }
    int ex = s[threadIdx.x] - c + g_bsums[blockIdx.x];
    if (i < N) {
        g_rowptr[i] = ex;
        g_cursor[i] = ex;
        g_deg[i] = (float)c;
        if (i == N - 1) g_rowptr[N] = ex + c;
    }
}

__global__ void k_fill(const int* __restrict__ src, const int* __restrict__ dst, int E) {
    for (int e = blockIdx.x * blockDim.x + threadIdx.x; e < E;
         e += gridDim.x * blockDim.x) {
        int d = __ldg(dst + e);
        int p = atomicAdd(&g_cursor[d], 1);
        g_perm[p] = __ldg(src + e);
    }
}

// ---------------- gather: agg[n] = y[n] + sum over in-neighbors of y[src] ----------------
__global__ void k_gather(int N) {
    int t = blockIdx.x * blockDim.x + threadIdx.x;
    int n = t >> 3, g = t & 7;
    if (n >= N) return;
    int beg = __ldg(g_rowptr + n), end = __ldg(g_rowptr + n + 1);
    float4 acc = ((const float4*)g_y)[(size_t)n * 8 + g];  // self row
    int p = beg;
    for (; p + 1 < end; p += 2) {
        int s0 = __ldg(g_perm + p);
        int s1 = __ldg(g_perm + p + 1);
        float4 v0 = *(const float4*)(g_y + (size_t)s0 * PAD + g * 4);
        float4 v1 = *(const float4*)(g_y + (size_t)s1 * PAD + g * 4);
        acc.x += v0.x + v1.x;
        acc.y += v0.y + v1.y;
        acc.z += v0.z + v1.z;
        acc.w += v0.w + v1.w;
    }
    if (p < end) {
        int s0 = __ldg(g_perm + p);
        float4 v0 = *(const float4*)(g_y + (size_t)s0 * PAD + g * 4);
        acc.x += v0.x;
        acc.y += v0.y;
        acc.z += v0.z;
        acc.w += v0.w;
    }
    ((float4*)g_agg)[(size_t)n * 8 + g] = acc;
}

// ---------------- MLP with fused BN-affine input + block-local column stats ----------------
__global__ void __launch_bounds__(128) k_mlp(const float* __restrict__ W1,
                                             const float* __restrict__ b1,
                                             const float* __restrict__ W2,
                                             const float* __restrict__ b2,
                                             const float* __restrict__ gammaP,
                                             const float* __restrict__ betaP,
                                             const float* __restrict__ sumsP,
                                             float* __restrict__ partial,
                                             int N, float invN) {
    __shared__ float sW1[DIM * PAD], sW2[DIM * PAD];
    __shared__ float sb1[PAD], sb2[PAD], ssc[PAD], ssf[PAD];
    __shared__ float ssum[64];
    for (int idx = threadIdx.x; idx < DIM * DIM; idx += 128) {
        int i = idx / DIM, o = idx % DIM;
        sW1[i * PAD + o] = W1[idx];
        sW2[i * PAD + o] = W2[idx];
    }
    if (threadIdx.x < 64) ssum[threadIdx.x] = 0.f;
    if (threadIdx.x < PAD) {
        int c = threadIdx.x;
        sb1[c] = (c < DIM) ? b1[c] : 0.f;
        sb2[c] = (c < DIM) ? b2[c] : 0.f;
        float sc = 0.f, sf = 0.f;
        if (c < DIM) {
            sc = 1.f;
            if (sumsP) {
                float m = sumsP[c] * invN;
                float var = sumsP[PAD + c] * invN - m * m;
                float istd = rsqrtf(var + BN_EPS);
                sc = gammaP[c] * istd;
                sf = betaP[c] - m * sc;
            }
        }
        ssc[c] = sc;
        ssf[c] = sf;
    }
    __syncthreads();

    int n = blockIdx.x * 128 + threadIdx.x;
    bool act = n < N;

    float h[PAD];
    if (act) {
        const float4* ar = (const float4*)(g_agg + (size_t)n * PAD);
        float dp1 = g_deg[n] + 1.f;
#pragma unroll
        for (int g = 0; g < 8; g++) {
            float4 s = ar[g];
            int c = 4 * g;
            h[c + 0] = ssc[c + 0] * s.x + dp1 * ssf[c + 0];
            h[c + 1] = ssc[c + 1] * s.y + dp1 * ssf[c + 1];
            h[c + 2] = ssc[c + 2] * s.z + dp1 * ssf[c + 2];
            h[c + 3] = ssc[c + 3] * s.w + dp1 * ssf[c + 3];
        }
    } else {
#pragma unroll
        for (int c = 0; c < PAD; c++) h[c] = 0.f;
    }

    float acc[DIM];
#pragma unroll
    for (int o = 0; o < DIM; o++) acc[o] = sb1[o];
#pragma unroll
    for (int i = 0; i < DIM; i++) {
        float xi = h[i];
        const float4* wr = (const float4*)(sW1 + i * PAD);
#pragma unroll
        for (int gq = 0; gq < 8; gq++) {
            float4 w = wr[gq];
            int o = gq * 4;
            acc[o + 0] += xi * w.x;
            acc[o + 1] += xi * w.y;
            acc[o + 2] += xi * w.z;
            if (o + 3 < DIM) acc[o + 3] += xi * w.w;
        }
    }
    float tt[DIM];
#pragma unroll
    for (int o = 0; o < DIM; o++) tt[o] = fmaxf(acc[o], 0.f);

#pragma unroll
    for (int o = 0; o < DIM; o++) acc[o] = sb2[o];
#pragma unroll
    for (int i = 0; i < DIM; i++) {
        float xi = tt[i];
        const float4* wr = (const float4*)(sW2 + i * PAD);
#pragma unroll
        for (int gq = 0; gq < 8; gq++) {
            float4 w = wr[gq];
            int o = gq * 4;
            acc[o + 0] += xi * w.x;
            acc[o + 1] += xi * w.y;
            acc[o + 2] += xi * w.z;
            if (o + 3 < DIM) acc[o + 3] += xi * w.w;
        }
    }

    float yv[PAD];
#pragma unroll
    for (int o = 0; o < DIM; o++) yv[o] = act ? fmaxf(acc[o], 0.f) : 0.f;
    yv[31] = 0.f;

    if (act) {
        float4* outp = (float4*)(g_y + (size_t)n * PAD);
#pragma unroll
        for (int g = 0; g < 8; g++)
            outp[g] = make_float4(yv[4 * g], yv[4 * g + 1], yv[4 * g + 2], yv[4 * g + 3]);
    }

    // column stats: warp shuffle -> smem (4 atomics/addr) -> per-block partials
#pragma unroll
    for (int c = 0; c < DIM; c++) {
        float s = yv[c];
        float q = s * s;
#pragma unroll
        for (int o = 16; o > 0; o >>= 1) {
            s += __shfl_xor_sync(0xffffffffu, s, o);
            q += __shfl_xor_sync(0xffffffffu, q, o);
        }
        if ((threadIdx.x & 31) == 0) {
            atomicAdd(&ssum[c], s);
            atomicAdd(&ssum[PAD + c], q);
        }
    }
    __syncthreads();
    if (threadIdx.x < 64)
        partial[(size_t)blockIdx.x * 64 + threadIdx.x] = ssum[threadIdx.x];
}

// ---------------- reduce per-block partials into g_sums[l*64..] ----------------
__global__ void k_reduce(float* __restrict__ out, int NPB) {
    int slot = blockIdx.x;  // 64 blocks
    float s = 0.f;
    for (int i = threadIdx.x; i < NPB; i += blockDim.x)
        s += g_partial[(size_t)i * 64 + slot];
#pragma unroll
    for (int o = 16; o > 0; o >>= 1) s += __shfl_xor_sync(0xffffffffu, s, o);
    __shared__ float sh[8];
    if ((threadIdx.x & 31) == 0) sh[threadIdx.x >> 5] = s;
    __syncthreads();
    if (threadIdx.x == 0) {
        float t = 0.f;
#pragma unroll
        for (int w = 0; w < 8; w++) t += sh[w];
        out[slot] = t;
    }
}

// ---------------- pooling: raw sums + counts, warp-aggregated ----------------
__global__ void k_pool(const int* __restrict__ batch, int N) {
    int t = blockIdx.x * blockDim.x + threadIdx.x;
    int n = t >> 3, g = t & 7, lane = threadIdx.x & 31;
    int b = -1;
    float4 v = make_float4(0.f, 0.f, 0.f, 0.f);
    if (n < N) {
        b = __ldg(batch + n);
        v = ((const float4*)g_y)[(size_t)n * 8 + g];
    }
    int b1 = __shfl_xor_sync(0xffffffffu, b, 8);
    int b2 = __shfl_xor_sync(0xffffffffu, b, 16);
    int b3 = __shfl_xor_sync(0xffffffffu, b, 24);
    bool allsame = (b == b1) && (b == b2) && (b == b3);
    if (allsame) {
        v.x += __shfl_xor_sync(0xffffffffu, v.x, 8);
        v.y += __shfl_xor_sync(0xffffffffu, v.y, 8);
        v.z += __shfl_xor_sync(0xffffffffu, v.z, 8);
        v.w += __shfl_xor_sync(0xffffffffu, v.w, 8);
        v.x += __shfl_xor_sync(0xffffffffu, v.x, 16);
        v.y += __shfl_xor_sync(0xffffffffu, v.y, 16);
        v.z += __shfl_xor_sync(0xffffffffu, v.z, 16);
        v.w += __shfl_xor_sync(0xffffffffu, v.w, 16);
        if (b >= 0 && lane < 8) {
            float* p = g_pooled + (size_t)b * PAD + g * 4;
            atomicAdd(p + 0, v.x);
            atomicAdd(p + 1, v.y);
            atomicAdd(p + 2, v.z);
            if (g < 7) atomicAdd(p + 3, v.w);
            if (lane == 0) atomicAdd(&g_gcnt[b], 4.f);
        }
    } else {
        if (b >= 0) {
            float* p = g_pooled + (size_t)b * PAD + g * 4;
            atomicAdd(p + 0, v.x);
            atomicAdd(p + 1, v.y);
            atomicAdd(p + 2, v.z);
            if (g < 7) atomicAdd(p + 3, v.w);
            if (g == 0) atomicAdd(&g_gcnt[b], 1.f);
        }
    }
}

// ---------------- per-graph fc with layer-4 BN affine applied to pooled ----------------
__global__ void k_fcbr(const float* __restrict__ W, const float* __restrict__ bb,
                       const float* __restrict__ gamma4, const float* __restrict__ beta4,
                       float* __restrict__ out, int G, float invN) {
    __shared__ float p[PAD];
    int g = blockIdx.x;
    if (threadIdx.x < PAD) {
        int c = threadIdx.x;
        float val = 0.f;
        if (c < DIM) {
            const float* s = g_sums + 4 * 64;
            float m = s[c] * invN;
            float var = s[PAD + c] * invN - m * m;
            float istd = rsqrtf(var + BN_EPS);
            float sc = gamma4[c] * istd;
            float sf = beta4[c] - m * sc;
            val = g_pooled[g * PAD + c] * sc + g_gcnt[g] * sf;
        }
        p[c] = val;
    }
    __syncthreads();
    int o = threadIdx.x;
    float acc = __ldg(bb + o);
#pragma unroll
    for (int i = 0; i < DIM; i++) acc += p[i] * __ldg(W + i * 256 + o);
    out[g * 256 + o] = fmaxf(acc, 0.f);
}

// ---------------- tiled SGEMM: C = act((A [+A2]) @ B + bias) ----------------
template <bool SUM2, bool RELU>
__global__ void k_gemm(const float* __restrict__ A, const float* __restrict__ A2,
                       const float* __restrict__ B, const float* __restrict__ bias,
                       float* __restrict__ C, int M, int N, int K) {
    const int BM = 64, BN = 64, BK = 16;
    __shared__ float As[BK][BM];
    __shared__ float Bs[BK][BN];
    int tx = threadIdx.x % 16, ty = threadIdx.x / 16;
    int row0 = blockIdx.y * BM, col0 = blockIdx.x * BN;
    float acc[4][4] = {};
    for (int k0 = 0; k0 < K; k0 += BK) {
        for (int i = threadIdx.x; i < BM * BK; i += 256) {
            int r = i / BK, c = i % BK;
            float v = A[(size_t)(row0 + r) * K + k0 + c];
            if (SUM2) v += A2[(size_t)(row0 + r) * K + k0 + c];
            As[c][r] = v;
        }
        for (int i = threadIdx.x; i < BK * BN; i += 256) {
            int r = i / BN, c = i % BN;
            Bs[r][c] = B[(size_t)(k0 + r) * N + col0 + c];
        }
        __syncthreads();
#pragma unroll
        for (int k = 0; k < BK; k++) {
            float a[4], bv[4];
#pragma unroll
            for (int u = 0; u < 4; u++) a[u] = As[k][ty * 4 + u];
#pragma unroll
            for (int u = 0; u < 4; u++) bv[u] = Bs[k][tx * 4 + u];
#pragma unroll
            for (int u = 0; u < 4; u++)
#pragma unroll
                for (int w = 0; w < 4; w++) acc[u][w] += a[u] * bv[w];
        }
        __syncthreads();
    }
#pragma unroll
    for (int u = 0; u < 4; u++)
#pragma unroll
        for (int w = 0; w < 4; w++) {
            int r = row0 + ty * 4 + u;
            int cc = col0 + tx * 4 + w;
            float val = acc[u][w] + bias[cc];
            if (RELU) val = fmaxf(val, 0.f);
            C[(size_t)r * N + cc] = val;
        }
}

// ---------------- final projection ----------------
__global__ void k_out(const float* __restrict__ W, const float* __restrict__ b,
                      float* __restrict__ out, int G) {
    __shared__ float sW[512];
    for (int i = threadIdx.x; i < 512; i += blockDim.x) sW[i] = W[i];
    __syncthreads();
    int g = blockIdx.x * blockDim.x + threadIdx.x;
    if (g >= G) return;
    const float4* row = (const float4*)(g_c2 + (size_t)g * 256);
    float a0 = b[0], a1 = b[1];
#pragma unroll 8
    for (int i = 0; i < 64; i++) {
        float4 v = row[i];
        int o = i * 4;
        a0 += v.x * sW[2 * o + 0] + v.y * sW[2 * o + 2] + v.z * sW[2 * o + 4] + v.w * sW[2 * o + 6];
        a1 += v.x * sW[2 * o + 1] + v.y * sW[2 * o + 3] + v.z * sW[2 * o + 5] + v.w * sW[2 * o + 7];
    }
    out[g * 2 + 0] = a0;
    out[g * 2 + 1] = a1;
}

// ---------------- launch ----------------
extern "C" void kernel_launch(void* const* d_in, const int* in_sizes, int n_in,
                              void* d_out, int out_size) {
    const float* x_a = (const float*)d_in[0];
    const int* ei_a = (const int*)d_in[1];
    const int* batch_a = (const int*)d_in[2];
    const float* x_b = (const float*)d_in[3];
    const int* ei_b = (const int*)d_in[4];
    const int* batch_b = (const int*)d_in[5];
    const float* W1s = (const float*)d_in[6];
    const float* b1s = (const float*)d_in[7];
    const float* W2s = (const float*)d_in[8];
    const float* b2s = (const float*)d_in[9];
    const float* gammas = (const float*)d_in[10];
    const float* betas = (const float*)d_in[11];
    const float* fcxW = (const float*)d_in[12];
    const float* fcxb = (const float*)d_in[13];
    const float* fc1W = (const float*)d_in[14];
    const float* fc1b = (const float*)d_in[15];
    const float* fc2W = (const float*)d_in[16];
    const float* fc2b = (const float*)d_in[17];
    const float* outW = (const float*)d_in[18];
    const float* outb = (const float*)d_in[19];

    int N = in_sizes[0] / DIM;
    int E = in_sizes[1] / 2;
    int G = out_size / 2;
    float invN = 1.f / (float)N;
    int NB = (N + 511) / 512;
    int NPB = (N + 127) / 128;

    float* sums_ptr;
    float* ha_ptr;
    float* hb_ptr;
    float* c1_ptr;
    float* c2_ptr;
    float* partial_ptr;
    cudaGetSymbolAddress((void**)&sums_ptr, g_sums);
    cudaGetSymbolAddress((void**)&ha_ptr, g_ha);
    cudaGetSymbolAddress((void**)&hb_ptr, g_hb);
    cudaGetSymbolAddress((void**)&c1_ptr, g_c1);
    cudaGetSymbolAddress((void**)&c2_ptr, g_c2);
    cudaGetSymbolAddress((void**)&partial_ptr, g_partial);

    for (int br = 0; br < 2; br++) {
        const float* x = br ? x_b : x_a;
        const int* ei = br ? ei_b : ei_a;
        const int* batch = br ? batch_b : batch_a;
        float* h = br ? hb_ptr : ha_ptr;

        k_init<<<2048, 256>>>(x, N);
        k_count<<<2048, 256>>>(ei + E, E);
        k_scan1<<<NB, 512>>>(N);
        k_scan2<<<1, 1024>>>(NB);
        k_scan3<<<NB, 512>>>(N);
        k_fill<<<2048, 256>>>(ei, ei + E, E);

        for (int l = 0; l < 5; l++) {
            k_gather<<<(N * 8 + 255) / 256, 256>>>(N);
            const float* sumsP = (l == 0) ? nullptr : sums_ptr + (l - 1) * 64;
            const float* gP = (l == 0) ? nullptr : gammas + (l - 1) * DIM;
            const float* bP = (l == 0) ? nullptr : betas + (l - 1) * DIM;
            k_mlp<<<NPB, 128>>>(W1s + l * DIM * DIM, b1s + l * DIM,
                                W2s + l * DIM * DIM, b2s + l * DIM,
                                gP, bP, sumsP, partial_ptr, N, invN);
            k_reduce<<<64, 256>>>(sums_ptr + l * 64, NPB);
        }
        k_pool<<<(N * 8 + 255) / 256, 256>>>(batch, N);
        k_fcbr<<<G, 256>>>(fcxW, fcxb, gammas + 4 * DIM, betas + 4 * DIM, h, G, invN);
    }

    dim3 g1(1024 / 64, G / 64);
    k_gemm<true, true><<<g1, 256>>>(ha_ptr, hb_ptr, fc1W, fc1b, c1_ptr, G, 1024, 256);
    dim3 g2(256 / 64, G / 64);
    k_gemm<false, true><<<g2, 256>>>(c1_ptr, nullptr, fc2W, fc2b, c2_ptr, G, 256, 1024);
    k_out<<<(G + 255) / 256, 256>>>(outW, outb, (float*)d_out, G);
}